// round 8
// baseline (speedup 1.0000x reference)
#include <cuda_runtime.h>

// out[b] = sum_k x[b,k] * S[k],  S[k] = sum_h W[h,k]   (scale 0.5*2.0 == 1.0)
// Two HBM-bound passes. This round: matvec restructured so the streaming
// loop has NO reductions/barriers (deferred reduce) -> full-duty DRAM.

#define BATCH 4096
#define IN    4096
#define HID   4096
#define RPC   8            // rows per CTA in matvec

__device__ __align__(16) float g_S[IN];

// Column-sum of W [HID, IN]. grid=(4, 256), block=256, 16 rows per CTA.
__global__ void __launch_bounds__(256, 4) colsum_kernel(const float* __restrict__ W) {
    int k4 = blockIdx.x * blockDim.x + threadIdx.x;   // float4 index along k
    int h0 = blockIdx.y * 16;

    const float4* Wv = reinterpret_cast<const float4*>(W);
    const int stride4 = IN / 4;
    long base = (long)h0 * stride4 + k4;

    float4 acc = make_float4(0.f, 0.f, 0.f, 0.f);
    #pragma unroll
    for (int g = 0; g < 2; g++) {
        float4 v[8];
        #pragma unroll
        for (int r = 0; r < 8; r++)
            v[r] = __ldcs(&Wv[base + (long)(g * 8 + r) * stride4]);
        #pragma unroll
        for (int r = 0; r < 8; r++) {
            acc.x += v[r].x; acc.y += v[r].y; acc.z += v[r].z; acc.w += v[r].w;
        }
    }
    float* dst = &g_S[k4 * 4];
    asm volatile("red.global.add.v4.f32 [%0], {%1, %2, %3, %4};"
                 :: "l"(dst), "f"(acc.x), "f"(acc.y), "f"(acc.z), "f"(acc.w)
                 : "memory");
}

// Matvec, deferred reduction. 512 CTAs x 256 threads; CTA owns rows
// [8*blockIdx.x, 8*blockIdx.x+8). Streaming phase writes per-thread partials
// to smem with no barriers; one reduce pass at the end.
__global__ void __launch_bounds__(256) matvec_kernel(const float* __restrict__ x,
                                                     float* __restrict__ out) {
    __shared__ float sS[IN];              // 16 KB
    __shared__ float part[RPC][256];      // 8 KB

    const int tid  = threadIdx.x;
    const int lane = tid & 31;
    const int wid  = tid >> 5;

    // Preload S (L2-hot).
    #pragma unroll
    for (int i = tid; i < IN / 4; i += 256)
        reinterpret_cast<float4*>(sS)[i] = reinterpret_cast<const float4*>(g_S)[i];
    __syncthreads();

    const float4* xv = reinterpret_cast<const float4*>(x);
    const float4* Ss = reinterpret_cast<const float4*>(sS);
    const long b0 = (long)blockIdx.x * RPC;

    // Phase A: pure streaming, 2 rows per step, 8 front-batched DRAM loads.
    #pragma unroll
    for (int r = 0; r < RPC; r += 2) {
        long base0 = (b0 + r)     * (IN / 4);
        long base1 = (b0 + r + 1) * (IN / 4);

        float4 v0[4], v1[4];
        #pragma unroll
        for (int j = 0; j < 4; j++) v0[j] = __ldcs(&xv[base0 + tid + j * 256]);
        #pragma unroll
        for (int j = 0; j < 4; j++) v1[j] = __ldcs(&xv[base1 + tid + j * 256]);

        float s0 = 0.f, s1 = 0.f;
        #pragma unroll
        for (int j = 0; j < 4; j++) {
            float4 ss = Ss[tid + j * 256];
            s0 = fmaf(v0[j].x, ss.x, s0); s0 = fmaf(v0[j].y, ss.y, s0);
            s0 = fmaf(v0[j].z, ss.z, s0); s0 = fmaf(v0[j].w, ss.w, s0);
            s1 = fmaf(v1[j].x, ss.x, s1); s1 = fmaf(v1[j].y, ss.y, s1);
            s1 = fmaf(v1[j].z, ss.z, s1); s1 = fmaf(v1[j].w, ss.w, s1);
        }
        part[r][tid]     = s0;            // no barrier — each thread owns its slot
        part[r + 1][tid] = s1;
    }
    __syncthreads();

    // Phase B: warp w reduces row w (8 warps, 8 rows). Conflict-free LDS.
    float s = 0.f;
    #pragma unroll
    for (int j = 0; j < 8; j++)
        s += part[wid][lane + j * 32];
    #pragma unroll
    for (int off = 16; off > 0; off >>= 1)
        s += __shfl_xor_sync(0xFFFFFFFFu, s, off);
    if (lane == 0) out[b0 + wid] = s;
}

extern "C" void kernel_launch(void* const* d_in, const int* in_sizes, int n_in,
                              void* d_out, int out_size) {
    const float* x = (const float*)d_in[0];
    const float* W = (const float*)d_in[1];
    float* out = (float*)d_out;

    void* s_ptr = nullptr;
    cudaGetSymbolAddress(&s_ptr, g_S);
    cudaMemsetAsync(s_ptr, 0, IN * sizeof(float));

    dim3 cs_grid(IN / (256 * 4), HID / 16);
    colsum_kernel<<<cs_grid, 256>>>(W);

    matvec_kernel<<<BATCH / RPC, 256>>>(x, out);
}